// round 12
// baseline (speedup 1.0000x reference)
#include <cuda_runtime.h>
#include <math.h>

#define NUM_CURVES 256
#define N_CTRL 10
#define NUM_GAUSS 16384        // 256 curves * 64 points
#define IMG 256
#define TILE 16
#define NTILE (IMG / TILE)     // 16
#define NSEG 4                 // depth-range split per tile
#define GPS (NUM_GAUSS / NSEG) // 4096 gaussians per segment
#define WPG (NUM_GAUSS / 32)   // 512 mask words per tile
#define WPS (GPS / 32)         // 128 mask words per (tile,seg)
#define NPREP 128              // blocks that perform prep
#define CUT 4.5f
#define LOG2E 1.4426950408889634f

// ---------------- device globals (scratch; zero-initialized at load) --------
__device__ float2   g_mean[NUM_GAUSS];              // depth-sorted centers
__device__ float4   g_con[NUM_CURVES];              // {A2, B2, C2, log2(alpha) clamped}
__device__ float4   g_col[NUM_CURVES];              // {r, g, b, 0}
__device__ float2   g_ext[NUM_CURVES];              // {rx, ry}
__device__ unsigned g_mask[NTILE * NTILE * WPG];    // per-tile bitmask (idempotent OR)
__device__ float4   g_part[NSEG * IMG * IMG];       // per-segment partials {cr,cg,cb,T}
__device__ int      g_cnt[NTILE * NTILE];           // per-tile seg counters (self-reset)
__device__ int      g_ready;                        // prep-done counter (self-reset)
__device__ int      g_done;                         // tile-combine counter (self-reset)

__device__ __forceinline__ float sigmoidf_(float x) { return 1.0f / (1.0f + __expf(-x)); }
__device__ __forceinline__ float ftanh_(float x)    { return 1.0f - 2.0f / (__expf(2.0f * x) + 1.0f); }

// ---------------- single fused kernel ----------------
__global__ __launch_bounds__(128)
void fused(const float* __restrict__ ctrl,
           const float* __restrict__ feat,
           const float* __restrict__ chol,
           const float* __restrict__ opac,
           const float* __restrict__ depth,
           const float* __restrict__ bg,
           float* __restrict__ out)
{
    int tid  = threadIdx.x;               // 128 threads
    int lane = tid & 31;
    int wrp  = tid >> 5;
    int bidLin = (blockIdx.z * gridDim.y + blockIdx.y) * gridDim.x + blockIdx.x;

    __shared__ float  sd[NUM_CURVES];
    __shared__ int    sord[NUM_CURVES];
    __shared__ unsigned short slist[GPS];        // 8KB
    __shared__ float4 scul[128];                 // {mx, my, rx, ry}
    __shared__ float4 sb[128];                   // {A2, B2, C2, l2a}
    __shared__ float4 sc[128];                   // {r, g, b, -}
    __shared__ unsigned char widx[4 * 128];
    __shared__ int    s_wcnt[4];
    __shared__ int    s_cnt;
    __shared__ int    s_old;

    // ================= phase 1: prep (first NPREP blocks) =================
    if (bidLin < NPREP) {
        // depth sort: 128 threads load/rank 2 curves each
        sd[tid]       = depth[tid];
        sd[tid + 128] = depth[tid + 128];
        __syncthreads();
        #pragma unroll
        for (int h = 0; h < 2; h++) {
            int i  = tid + h * 128;
            float di = sd[i];
            int rank = 0;
            const float4* sd4 = reinterpret_cast<const float4*>(sd);
            #pragma unroll 8
            for (int j4 = 0; j4 < NUM_CURVES / 4; j4++) {
                float4 v = sd4[j4];
                int jb = j4 * 4;
                rank += (v.x < di) || (v.x == di && (jb + 0) < i);
                rank += (v.y < di) || (v.y == di && (jb + 1) < i);
                rank += (v.z < di) || (v.z == di && (jb + 2) < i);
                rank += (v.w < di) || (v.w == di && (jb + 3) < i);
            }
            sord[rank] = i;
        }
        __syncthreads();

        int g    = bidLin * 128 + tid;     // 128 blocks x 128 = 16384
        int slot = g >> 6;
        int pt   = g & 63;
        int c    = sord[slot];
        int seg  = pt >> 5;
        int s    = pt & 31;

        float c0 = chol[3*c + 0] + 0.5f;
        float c1 = chol[3*c + 1];
        float c2 = chol[3*c + 2] + 0.5f;
        float s00 = c0*c0, s01 = c0*c1, s11 = c1*c1 + c2*c2;
        float inv = 1.0f / (s00*s11 - s01*s01);
        float A = s11*inv, Bc = -s01*inv, C = s00*inv;
        float rx = sqrtf(2.0f * CUT * s00);
        float ry = sqrtf(2.0f * CUT * s11);

        if (pt == 0) {
            float al  = sigmoidf_(opac[c]);
            float l2a = fminf(log2f(al), log2f(0.999f));   // exact clamp hoist
            g_con[slot] = make_float4(0.5f*A*LOG2E, Bc*LOG2E, 0.5f*C*LOG2E, l2a);
            g_col[slot] = make_float4(sigmoidf_(feat[3*c+0]), sigmoidf_(feat[3*c+1]),
                                      sigmoidf_(feat[3*c+2]), 0.0f);
            g_ext[slot] = make_float2(rx, ry);
        }

        float t = 0.007f + (float)s * (0.986f / 31.0f);
        float u = 1.0f - t;
        float t2 = t*t, t3 = t2*t, t4 = t3*t, t5 = t4*t;
        float u2 = u*u, u3 = u2*u, u4 = u3*u, u5 = u4*u;
        float w0 = u5, w1 = 5.0f*t*u4, w2 = 10.0f*t2*u3,
              w3 = 10.0f*t3*u2, w4 = 5.0f*t4*u, w5 = t5;

        const float* cp = ctrl + c * N_CTRL * 2;
        int i0 = seg * 5;
        int i5 = (i0 + 5) % N_CTRL;
        float px = w0*cp[2*i0+0] + w1*cp[2*(i0+1)+0] + w2*cp[2*(i0+2)+0]
                 + w3*cp[2*(i0+3)+0] + w4*cp[2*(i0+4)+0] + w5*cp[2*i5+0];
        float py = w0*cp[2*i0+1] + w1*cp[2*(i0+1)+1] + w2*cp[2*(i0+2)+1]
                 + w3*cp[2*(i0+3)+1] + w4*cp[2*(i0+4)+1] + w5*cp[2*i5+1];

        float mx = (ftanh_(px) * 0.5f + 0.5f) * (float)IMG;
        float my = (ftanh_(py) * 0.5f + 0.5f) * (float)IMG;
        g_mean[g] = make_float2(mx, my);

        int tx0 = max(0, (int)floorf((mx - rx - 0.5f) / (float)TILE));
        int tx1 = min(NTILE - 1, (int)floorf((mx + rx - 0.5f) / (float)TILE));
        int ty0 = max(0, (int)floorf((my - ry - 0.5f) / (float)TILE));
        int ty1 = min(NTILE - 1, (int)floorf((my + ry - 0.5f) / (float)TILE));
        unsigned bit  = 1u << (g & 31);
        int      word = g >> 5;
        for (int ty = ty0; ty <= ty1; ty++)
            for (int tx = tx0; tx <= tx1; tx++)
                atomicOr(&g_mask[(ty * NTILE + tx) * WPG + word], bit);

        __threadfence();                   // release prep writes
        __syncthreads();
        if (tid == 0) atomicAdd(&g_ready, 1);
    }

    // ================= grid-wide wait (all blocks co-resident) =============
    if (tid == 0) {
        volatile int* rp = &g_ready;
        while (*rp < NPREP) __nanosleep(64);
    }
    __syncthreads();
    __threadfence();                       // acquire prep writes

    // ================= phase 2: render =================
    int qx   = (wrp & 1) * 8;
    int qy   = (wrp >> 1) * 8;
    int lx   = lane & 7;
    int gy   = lane >> 3;
    int seg  = blockIdx.z;
    int tile = blockIdx.y * NTILE + blockIdx.x;

    float X0  = (float)(blockIdx.x * TILE);
    float Y0  = (float)(blockIdx.y * TILE);
    float px  = X0 + (float)(qx + lx) + 0.5f;
    float py0 = Y0 + (float)(qy + 2*gy) + 0.5f;
    float py1 = py0 + 1.0f;
    float qcx = X0 + (float)qx + 4.0f;
    float qcy = Y0 + (float)qy + 4.0f;

    // --- expand bitmask to local-id list (order preserved) ---
    {
        unsigned word = g_mask[tile * WPG + seg * WPS + tid];
        int cnt = __popc(word);
        int scan = cnt;
        #pragma unroll
        for (int d = 1; d < 32; d <<= 1) {
            int v = __shfl_up_sync(0xFFFFFFFFu, scan, d);
            if (lane >= d) scan += v;
        }
        if (lane == 31) s_wcnt[wrp] = scan;
        __syncthreads();
        if (tid == 0) s_cnt = s_wcnt[0] + s_wcnt[1] + s_wcnt[2] + s_wcnt[3];
        int off = scan - cnt;
        #pragma unroll
        for (int k = 0; k < 4; k++) if (k < wrp) off += s_wcnt[k];
        int lb = tid * 32;
        while (word) {
            int b = __ffs(word) - 1;
            word &= word - 1;
            slist[off++] = (unsigned short)(lb + b);
        }
    }
    __syncthreads();

    int total = s_cnt;
    float T0 = 1.0f, cr0 = 0.0f, cg0 = 0.0f, cb0 = 0.0f;
    float T1 = 1.0f, cr1 = 0.0f, cg1 = 0.0f, cb1 = 0.0f;

    for (int base = 0; base < total; base += 128) {
        int n = min(128, total - base);
        if (tid < n) {
            int g    = seg * GPS + (int)slist[base + tid];
            int slot = g >> 6;
            float2 m  = g_mean[g];
            float2 ex = g_ext[slot];
            scul[tid] = make_float4(m.x, m.y, ex.x, ex.y);
            sb[tid]   = g_con[slot];
            sc[tid]   = g_col[slot];
        }
        __syncthreads();

        bool dead = (T0 < 1e-6f) && (T1 < 1e-6f);
        if (!__all_sync(0xFFFFFFFFu, dead)) {
            // per-warp 2D-cull compaction (order-preserving)
            int wn = 0;
            #pragma unroll
            for (int k = 0; k < 4; k++) {
                int idx = k * 32 + lane;
                bool ok = false;
                if (idx < n) {
                    float4 cu = scul[idx];
                    ok = (fabsf(cu.x - qcx) <= cu.z + 3.5f) &&
                         (fabsf(cu.y - qcy) <= cu.w + 3.5f);
                }
                unsigned mk = __ballot_sync(0xFFFFFFFFu, ok);
                if (ok)
                    widx[wrp * 128 + wn + __popc(mk & ((1u << lane) - 1u))] =
                        (unsigned char)idx;
                wn += __popc(mk);
            }
            __syncwarp();

            for (int j = 0; j < wn; j++) {
                int    idx = (int)widx[wrp * 128 + j];
                float4 cu  = scul[idx];                  // mx,my
                float4 b4  = sb[idx];                    // A2,B2,C2,l2a
                float4 c4  = sc[idx];                    // r,g,b
                float dx  = px  - cu.x;
                float dy0 = py0 - cu.y;
                float dy1 = py1 - cu.y;
                float e   = fmaf(-b4.x * dx, dx, b4.w);
                float bx  = b4.y * dx;
                float t0  = fmaf(b4.z, dy0, bx);
                float t1  = fmaf(b4.z, dy1, bx);
                float g0  = fmaf(-t0, dy0, e);
                float g1  = fmaf(-t1, dy1, e);
                float a0  = exp2f(g0);                   // alpha pre-clamped
                float a1  = exp2f(g1);
                float w0_ = a0 * T0;
                float w1_ = a1 * T1;
                cr0 = fmaf(w0_, c4.x, cr0); cg0 = fmaf(w0_, c4.y, cg0); cb0 = fmaf(w0_, c4.z, cb0);
                cr1 = fmaf(w1_, c4.x, cr1); cg1 = fmaf(w1_, c4.y, cg1); cb1 = fmaf(w1_, c4.z, cb1);
                T0 -= w0_;
                T1 -= w1_;
            }
        }

        if (__syncthreads_and((T0 < 1e-6f) & (T1 < 1e-6f))) break;
    }

    int pix0 = (blockIdx.y * TILE + qy + 2*gy) * IMG + (blockIdx.x * TILE + qx + lx);
    int pix1 = pix0 + IMG;
    g_part[seg * (IMG*IMG) + pix0] = make_float4(cr0, cg0, cb0, T0);
    g_part[seg * (IMG*IMG) + pix1] = make_float4(cr1, cg1, cb1, T1);

    // ---- last-block-done per-tile combine ----
    __threadfence();
    __syncthreads();
    if (tid == 0) s_old = atomicAdd(&g_cnt[tile], 1);
    __syncthreads();

    if (s_old == NSEG - 1) {
        __threadfence();
        float b0 = bg[0], b1 = bg[1], b2 = bg[2];
        #pragma unroll
        for (int k = 0; k < 2; k++) {
            int pix = k ? pix1 : pix0;
            float fr = 0.0f, fg = 0.0f, fb = 0.0f, fT = 1.0f;
            #pragma unroll
            for (int s = 0; s < NSEG; s++) {
                float4 p = g_part[s * (IMG*IMG) + pix];
                fr = fmaf(fT, p.x, fr);
                fg = fmaf(fT, p.y, fg);
                fb = fmaf(fT, p.z, fb);
                fT *= p.w;
            }
            int o = pix * 3;
            out[o + 0] = fminf(fmaxf(fmaf(fT, b0, fr), 0.0f), 1.0f);
            out[o + 1] = fminf(fmaxf(fmaf(fT, b1, fg), 0.0f), 1.0f);
            out[o + 2] = fminf(fmaxf(fmaf(fT, b2, fb), 0.0f), 1.0f);
        }
        if (tid == 0) {
            g_cnt[tile] = 0;                           // per-tile reset
            int d = atomicAdd(&g_done, 1);
            if (d == NTILE * NTILE - 1) {              // very last combiner:
                atomicSub(&g_ready, NPREP);            // safe: all blocks passed spin
                g_done = 0;                            // reset for next replay
            }
        }
    }
}

// ---------------- launch ----------------
extern "C" void kernel_launch(void* const* d_in, const int* in_sizes, int n_in,
                              void* d_out, int out_size)
{
    const float* ctrl  = (const float*)d_in[0];   // (256,10,2)
    const float* feat  = (const float*)d_in[1];   // (256,3)
    const float* chol  = (const float*)d_in[2];   // (256,3)
    const float* opac  = (const float*)d_in[3];   // (256,1)
    const float* depth = (const float*)d_in[4];   // (256,1)
    const float* bg    = (const float*)d_in[5];   // (3,)
    float* out = (float*)d_out;                   // (256,256,3)

    fused<<<dim3(NTILE, NTILE, NSEG), 128>>>(ctrl, feat, chol, opac, depth, bg, out);
}

// round 13
// speedup vs baseline: 1.2183x; 1.2183x over previous
#include <cuda_runtime.h>
#include <math.h>

#define NUM_CURVES 256
#define N_CTRL 10
#define NUM_GAUSS 16384        // 256 curves * 64 points
#define IMG 256
#define TILE 16
#define NTILE (IMG / TILE)     // 16
#define NSEG 4                 // depth-range split per tile
#define GPS (NUM_GAUSS / NSEG) // 4096 gaussians per segment
#define WPG (NUM_GAUSS / 32)   // 512 mask words per tile
#define WPS (GPS / 32)         // 128 mask words per (tile,seg)
#define CUT 4.5f
#define LOG2E 1.4426950408889634f

// ---------------- device globals (scratch; zero-initialized at load) --------
__device__ float2   g_mean[NUM_GAUSS];              // depth-sorted centers
__device__ float4   g_con[NUM_CURVES];              // {A2, B2, C2, log2(alpha) clamped}
__device__ float4   g_col[NUM_CURVES];              // {r, g, b, 0}
__device__ float2   g_ext[NUM_CURVES];              // {rx, ry}
__device__ unsigned g_mask[NTILE * NTILE * WPG];    // per-tile bitmask (idempotent OR)
__device__ float4   g_part[NSEG * IMG * IMG];       // per-segment partials {cr,cg,cb,T}
__device__ int      g_cnt[NTILE * NTILE];           // per-tile done counters (self-reset)

__device__ __forceinline__ float sigmoidf_(float x) { return 1.0f / (1.0f + __expf(-x)); }
__device__ __forceinline__ float ftanh_(float x)    { return 1.0f - 2.0f / (__expf(2.0f * x) + 1.0f); }

// ---------------- kernel 1: sort + params + means + binning ----------------
__global__ __launch_bounds__(256)
void prep(const float* __restrict__ ctrl,
          const float* __restrict__ feat,
          const float* __restrict__ chol,
          const float* __restrict__ opac,
          const float* __restrict__ depth)
{
    __shared__ float sd[NUM_CURVES];
    __shared__ int   sord[NUM_CURVES];   // rank -> original curve
    int i = threadIdx.x;

    sd[i] = depth[i];
    __syncthreads();
    float di = sd[i];
    int rank = 0;
    const float4* sd4 = reinterpret_cast<const float4*>(sd);
    #pragma unroll 8
    for (int j4 = 0; j4 < NUM_CURVES / 4; j4++) {
        float4 v = sd4[j4];
        int jb = j4 * 4;
        rank += (v.x < di) || (v.x == di && (jb + 0) < i);
        rank += (v.y < di) || (v.y == di && (jb + 1) < i);
        rank += (v.z < di) || (v.z == di && (jb + 2) < i);
        rank += (v.w < di) || (v.w == di && (jb + 3) < i);
    }
    sord[rank] = i;
    __syncthreads();

    // this block's gaussian (sorted order)
    int g    = blockIdx.x * 256 + i;
    int slot = g >> 6;           // sorted curve slot
    int pt   = g & 63;
    int c    = sord[slot];       // original curve
    int seg  = pt >> 5;
    int s    = pt & 31;

    // covariance / conic for curve c
    float c0 = chol[3*c + 0] + 0.5f;
    float c1 = chol[3*c + 1];
    float c2 = chol[3*c + 2] + 0.5f;
    float s00 = c0*c0, s01 = c0*c1, s11 = c1*c1 + c2*c2;   // covariance
    float inv = 1.0f / (s00*s11 - s01*s01);
    float A = s11*inv, Bc = -s01*inv, C = s00*inv;          // conic
    // exact per-axis extents of {0.5 A dx^2 + B dx dy + 0.5 C dy^2 <= CUT}
    float rx = sqrtf(2.0f * CUT * s00);
    float ry = sqrtf(2.0f * CUT * s11);

    // one writer per sorted slot (pt==0); values for curve c == sord[slot]
    if (pt == 0) {
        float al = sigmoidf_(opac[c]);
        // exact clamp hoist: exp(-p) <= 1, so min(alpha,0.999)*exp(-p)
        // == min(alpha*exp(-p), 0.999) everywhere it binds
        float l2a = fminf(log2f(al), log2f(0.999f));
        g_con[slot] = make_float4(0.5f*A*LOG2E, Bc*LOG2E, 0.5f*C*LOG2E, l2a);
        g_col[slot] = make_float4(sigmoidf_(feat[3*c+0]), sigmoidf_(feat[3*c+1]),
                                  sigmoidf_(feat[3*c+2]), 0.0f);
        g_ext[slot] = make_float2(rx, ry);
    }

    // Bezier mean
    float t = 0.007f + (float)s * (0.986f / 31.0f);
    float u = 1.0f - t;
    float t2 = t*t, t3 = t2*t, t4 = t3*t, t5 = t4*t;
    float u2 = u*u, u3 = u2*u, u4 = u3*u, u5 = u4*u;
    float w0 = u5, w1 = 5.0f*t*u4, w2 = 10.0f*t2*u3,
          w3 = 10.0f*t3*u2, w4 = 5.0f*t4*u, w5 = t5;

    const float* cp = ctrl + c * N_CTRL * 2;
    int i0 = seg * 5;
    int i5 = (i0 + 5) % N_CTRL;
    float px = w0*cp[2*i0+0] + w1*cp[2*(i0+1)+0] + w2*cp[2*(i0+2)+0]
             + w3*cp[2*(i0+3)+0] + w4*cp[2*(i0+4)+0] + w5*cp[2*i5+0];
    float py = w0*cp[2*i0+1] + w1*cp[2*(i0+1)+1] + w2*cp[2*(i0+2)+1]
             + w3*cp[2*(i0+3)+1] + w4*cp[2*(i0+4)+1] + w5*cp[2*i5+1];

    float mx = (ftanh_(px) * 0.5f + 0.5f) * (float)IMG;
    float my = (ftanh_(py) * 0.5f + 0.5f) * (float)IMG;
    g_mean[g] = make_float2(mx, my);

    // binning with per-axis extents
    int tx0 = max(0, (int)floorf((mx - rx - 0.5f) / (float)TILE));
    int tx1 = min(NTILE - 1, (int)floorf((mx + rx - 0.5f) / (float)TILE));
    int ty0 = max(0, (int)floorf((my - ry - 0.5f) / (float)TILE));
    int ty1 = min(NTILE - 1, (int)floorf((my + ry - 0.5f) / (float)TILE));
    unsigned bit  = 1u << (g & 31);
    int      word = g >> 5;
    for (int ty = ty0; ty <= ty1; ty++)
        for (int tx = tx0; tx <= tx1; tx++)
            atomicOr(&g_mask[(ty * NTILE + tx) * WPG + word], bit);
}

// ---------------- kernel 2: quadrant-warp render + fused combine ------------
__global__ __launch_bounds__(128)
void render(const float* __restrict__ bg, float* __restrict__ out)
{
    int tid  = threadIdx.x;               // 128 threads
    int lane = tid & 31;
    int wrp  = tid >> 5;                  // warp -> 8x8 quadrant
    int qx   = (wrp & 1) * 8;
    int qy   = (wrp >> 1) * 8;
    int lx   = lane & 7;                  // 0..7 within quadrant
    int gy   = lane >> 3;                 // 0..3 row-pair
    int seg  = blockIdx.z;
    int tile = blockIdx.y * NTILE + blockIdx.x;

    float X0  = (float)(blockIdx.x * TILE);
    float Y0  = (float)(blockIdx.y * TILE);
    float px  = X0 + (float)(qx + lx) + 0.5f;
    float py0 = Y0 + (float)(qy + 2*gy) + 0.5f;
    float py1 = py0 + 1.0f;
    float qcx = X0 + (float)qx + 4.0f;    // quadrant center; halfspan 3.5
    float qcy = Y0 + (float)qy + 4.0f;

    __shared__ unsigned short slist[GPS];        // segment-local survivor ids, 8KB
    __shared__ float4 scul[128];                 // {mx, my, rx, ry}
    __shared__ float4 sb[128];                   // {A2, B2, C2, l2a}
    __shared__ float4 sc[128];                   // {r, g, b, -}
    __shared__ unsigned char widx[4 * 128];      // per-warp compacted chunk indices
    __shared__ int    s_wcnt[4];
    __shared__ int    s_cnt;
    __shared__ int    s_old;

    // --- expand bitmask to local-id list (128 threads, order preserved) ---
    {
        unsigned word = g_mask[tile * WPG + seg * WPS + tid];
        int cnt = __popc(word);
        int scan = cnt;
        #pragma unroll
        for (int d = 1; d < 32; d <<= 1) {
            int v = __shfl_up_sync(0xFFFFFFFFu, scan, d);
            if (lane >= d) scan += v;
        }
        if (lane == 31) s_wcnt[wrp] = scan;
        __syncthreads();
        if (tid == 0) s_cnt = s_wcnt[0] + s_wcnt[1] + s_wcnt[2] + s_wcnt[3];
        int off = scan - cnt;
        #pragma unroll
        for (int k = 0; k < 4; k++) if (k < wrp) off += s_wcnt[k];
        int lb = tid * 32;
        while (word) {
            int b = __ffs(word) - 1;
            word &= word - 1;
            slist[off++] = (unsigned short)(lb + b);
        }
    }
    __syncthreads();

    int total = s_cnt;
    float T0 = 1.0f, cr0 = 0.0f, cg0 = 0.0f, cb0 = 0.0f;
    float T1 = 1.0f, cr1 = 0.0f, cg1 = 0.0f, cb1 = 0.0f;

    for (int base = 0; base < total; base += 128) {
        int n = min(128, total - base);
        if (tid < n) {
            int g    = seg * GPS + (int)slist[base + tid];
            int slot = g >> 6;
            float2 m  = g_mean[g];
            float2 ex = g_ext[slot];
            scul[tid] = make_float4(m.x, m.y, ex.x, ex.y);
            sb[tid]   = g_con[slot];
            sc[tid]   = g_col[slot];
        }
        __syncthreads();

        bool dead = (T0 < 1e-6f) && (T1 < 1e-6f);
        if (!__all_sync(0xFFFFFFFFu, dead)) {
            // --- per-warp 2D-cull compaction (order-preserving) ---
            int wn = 0;
            #pragma unroll
            for (int k = 0; k < 4; k++) {
                int idx = k * 32 + lane;
                bool ok = false;
                if (idx < n) {
                    float4 cu = scul[idx];
                    ok = (fabsf(cu.x - qcx) <= cu.z + 3.5f) &&
                         (fabsf(cu.y - qcy) <= cu.w + 3.5f);
                }
                unsigned mk = __ballot_sync(0xFFFFFFFFu, ok);
                if (ok)
                    widx[wrp * 128 + wn + __popc(mk & ((1u << lane) - 1u))] =
                        (unsigned char)idx;
                wn += __popc(mk);
            }
            __syncwarp();

            for (int j = 0; j < wn; j++) {
                int    idx = (int)widx[wrp * 128 + j];
                float4 cu  = scul[idx];                  // mx,my
                float4 b4  = sb[idx];                    // A2,B2,C2,l2a
                float4 c4  = sc[idx];                    // r,g,b
                float dx  = px  - cu.x;
                float dy0 = py0 - cu.y;
                float dy1 = py1 - cu.y;
                float e   = fmaf(-b4.x * dx, dx, b4.w);  // l2a - A2*dx^2
                float bx  = b4.y * dx;                   // B2*dx
                float t0  = fmaf(b4.z, dy0, bx);
                float t1  = fmaf(b4.z, dy1, bx);
                float g0  = fmaf(-t0, dy0, e);
                float g1  = fmaf(-t1, dy1, e);
                float a0  = exp2f(g0);                   // alpha pre-clamped at prep
                float a1  = exp2f(g1);
                float w0_ = a0 * T0;
                float w1_ = a1 * T1;
                cr0 = fmaf(w0_, c4.x, cr0); cg0 = fmaf(w0_, c4.y, cg0); cb0 = fmaf(w0_, c4.z, cb0);
                cr1 = fmaf(w1_, c4.x, cr1); cg1 = fmaf(w1_, c4.y, cg1); cb1 = fmaf(w1_, c4.z, cb1);
                T0 -= w0_;
                T1 -= w1_;
            }
        }

        if (__syncthreads_and((T0 < 1e-6f) & (T1 < 1e-6f))) break;  // guards smem reuse
    }

    int pix0 = (blockIdx.y * TILE + qy + 2*gy) * IMG + (blockIdx.x * TILE + qx + lx);
    int pix1 = pix0 + IMG;
    g_part[seg * (IMG*IMG) + pix0] = make_float4(cr0, cg0, cb0, T0);
    g_part[seg * (IMG*IMG) + pix1] = make_float4(cr1, cg1, cb1, T1);

    // ---- last-block-done combine ----
    __threadfence();
    __syncthreads();
    if (tid == 0) s_old = atomicAdd(&g_cnt[tile], 1);
    __syncthreads();

    if (s_old == NSEG - 1) {
        __threadfence();
        float b0 = bg[0], b1 = bg[1], b2 = bg[2];
        #pragma unroll
        for (int k = 0; k < 2; k++) {
            int pix = k ? pix1 : pix0;
            float fr = 0.0f, fg = 0.0f, fb = 0.0f, fT = 1.0f;
            #pragma unroll
            for (int s = 0; s < NSEG; s++) {
                float4 p = g_part[s * (IMG*IMG) + pix];
                fr = fmaf(fT, p.x, fr);
                fg = fmaf(fT, p.y, fg);
                fb = fmaf(fT, p.z, fb);
                fT *= p.w;
            }
            int o = pix * 3;
            out[o + 0] = fminf(fmaxf(fmaf(fT, b0, fr), 0.0f), 1.0f);
            out[o + 1] = fminf(fmaxf(fmaf(fT, b1, fg), 0.0f), 1.0f);
            out[o + 2] = fminf(fmaxf(fmaf(fT, b2, fb), 0.0f), 1.0f);
        }
        if (tid == 0) g_cnt[tile] = 0;   // self-reset for next replay
    }
}

// ---------------- launch ----------------
extern "C" void kernel_launch(void* const* d_in, const int* in_sizes, int n_in,
                              void* d_out, int out_size)
{
    const float* ctrl  = (const float*)d_in[0];   // (256,10,2)
    const float* feat  = (const float*)d_in[1];   // (256,3)
    const float* chol  = (const float*)d_in[2];   // (256,3)
    const float* opac  = (const float*)d_in[3];   // (256,1)
    const float* depth = (const float*)d_in[4];   // (256,1)
    const float* bg    = (const float*)d_in[5];   // (3,)
    float* out = (float*)d_out;                   // (256,256,3)

    prep<<<64, 256>>>(ctrl, feat, chol, opac, depth);
    render<<<dim3(NTILE, NTILE, NSEG), 128>>>(bg, out);
}